// round 1
// baseline (speedup 1.0000x reference)
#include <cuda_runtime.h>
#include <math.h>

#define KSIZE 3
#define THRE_TIMES 5.0f
#define THRE_POINT 1000.0f

__global__ __launch_bounds__(256) void damaged_point_repair_kernel(
    const float* __restrict__ img, float* __restrict__ out, int H, int W)
{
    int qx = blockIdx.x * blockDim.x + threadIdx.x;   // quad-column index
    int r  = blockIdx.y * blockDim.y + threadIdx.y;   // row
    int Wq = W >> 2;
    if (qx >= Wq || r >= H) return;
    int c4 = qx << 2;

    // rowv[k][0..5] = cols c4-1 .. c4+4 of row r+k-1, zero-padded out of range
    float rowv[3][6];
#pragma unroll
    for (int k = 0; k < 3; ++k) {
        int rr = r + k - 1;
        if (rr < 0 || rr >= H) {
#pragma unroll
            for (int j = 0; j < 6; ++j) rowv[k][j] = 0.0f;
        } else {
            const float* p = img + (size_t)rr * W + c4;
            float4 cc = *reinterpret_cast<const float4*>(p);
            rowv[k][1] = cc.x; rowv[k][2] = cc.y;
            rowv[k][3] = cc.z; rowv[k][4] = cc.w;
            rowv[k][0] = (c4 > 0)     ? __ldg(p - 1) : 0.0f;
            rowv[k][5] = (c4 + 4 < W) ? __ldg(p + 4) : 0.0f;
        }
    }

    const bool rtop = (r == 0);
    const bool rbot = (r == H - 1);
    const float cnt_row = (float)((r > 0) + (r < H - 1));

    float o[4];
#pragma unroll
    for (int j = 0; j < 4; ++j) {
        int c = c4 + j;
        float v = rowv[1][j + 1];

        // 3x3 zero-padded box sum -> mean -> boundary coefficient
        float sum9 = rowv[0][j] + rowv[0][j + 1] + rowv[0][j + 2]
                   + rowv[1][j] + rowv[1][j + 1] + rowv[1][j + 2]
                   + rowv[2][j] + rowv[2][j + 1] + rowv[2][j + 2];
        float mean = sum9 * (1.0f / 9.0f);

        bool cl = (c == 0), cr = (c == W - 1);
        float coeff = 1.0f;
        if (rtop || rbot || cl || cr)
            coeff = ((rtop || rbot) && (cl || cr)) ? 2.25f : 1.5f;

        bool mask = (v > THRE_TIMES * mean * coeff) || (v > THRE_POINT);

        // 4-neighbor repair: floor(sum / valid_count)
        float nsum = rowv[0][j + 1] + rowv[2][j + 1] + rowv[1][j] + rowv[1][j + 2];
        float cnt  = cnt_row + (float)((c > 0) + (c < W - 1));
        float rep  = floorf(nsum / cnt);

        o[j] = mask ? rep : v;
    }

    float4 res = make_float4(o[0], o[1], o[2], o[3]);
    *reinterpret_cast<float4*>(out + (size_t)r * W + c4) = res;
}

extern "C" void kernel_launch(void* const* d_in, const int* in_sizes, int n_in,
                              void* d_out, int out_size)
{
    const float* img = (const float*)d_in[0];
    float* out = (float*)d_out;

    int n = in_sizes[0];
    // square image; derive side length robustly
    int W = (int)(sqrt((double)n) + 0.5);
    int H = n / W;

    dim3 block(64, 4);
    dim3 grid(((W >> 2) + block.x - 1) / block.x,
              (H + block.y - 1) / block.y);
    damaged_point_repair_kernel<<<grid, block>>>(img, out, H, W);
}

// round 2
// speedup vs baseline: 1.2612x; 1.2612x over previous
#include <cuda_runtime.h>
#include <math.h>

#define THRE_TIMES 5.0f
#define THRE_POINT 1000.0f
#define RPT 4   // output rows per thread

__global__ __launch_bounds__(256) void damaged_point_repair_kernel(
    const float* __restrict__ img, float* __restrict__ out, int H, int W)
{
    const int Wq = W >> 2;
    const int qx = blockIdx.x * blockDim.x + threadIdx.x;   // quad-column index
    if (qx >= Wq) return;
    const int c4 = qx << 2;
    const int r0 = (blockIdx.y * blockDim.y + threadIdx.y) * RPT;
    if (r0 >= H) return;

    const bool colEdge = (c4 == 0) | (c4 + 4 >= W);
    const bool rowEdge = (r0 == 0) | (r0 + RPT >= H);
    const bool edge = colEdge | rowEdge;

    // Rolling 3-row window: raw[s][0..5] = cols c4-1..c4+4 (zero padded),
    // hs[s][j] = horizontal 3-sum for output column c4+j.
    float raw[3][6];
    float hs[3][4];

#pragma unroll
    for (int s = 0; s < 2; ++s) {           // preload rows r0-1, r0
        int rr = r0 - 1 + s;
        if (rr < 0 || rr >= H) {
#pragma unroll
            for (int j = 0; j < 6; ++j) raw[s][j] = 0.0f;
        } else {
            const float* p = img + (size_t)rr * W + c4;
            float4 cc = *reinterpret_cast<const float4*>(p);
            raw[s][1] = cc.x; raw[s][2] = cc.y; raw[s][3] = cc.z; raw[s][4] = cc.w;
            raw[s][0] = (c4 > 0)     ? __ldg(p - 1) : 0.0f;
            raw[s][5] = (c4 + 4 < W) ? __ldg(p + 4) : 0.0f;
        }
#pragma unroll
        for (int j = 0; j < 4; ++j) hs[s][j] = raw[s][j] + raw[s][j + 1] + raw[s][j + 2];
    }

#pragma unroll
    for (int ri = 0; ri < RPT; ++ri) {
        const int r = r0 + ri;
        const int sUp = ri % 3, sMid = (ri + 1) % 3, sDn = (ri + 2) % 3;

        // load row r+1 into slot sDn
        {
            int rr = r + 1;
            if (rr >= H) {
#pragma unroll
                for (int j = 0; j < 6; ++j) raw[sDn][j] = 0.0f;
            } else {
                const float* p = img + (size_t)rr * W + c4;
                float4 cc = *reinterpret_cast<const float4*>(p);
                raw[sDn][1] = cc.x; raw[sDn][2] = cc.y; raw[sDn][3] = cc.z; raw[sDn][4] = cc.w;
                raw[sDn][0] = (c4 > 0)     ? __ldg(p - 1) : 0.0f;
                raw[sDn][5] = (c4 + 4 < W) ? __ldg(p + 4) : 0.0f;
            }
#pragma unroll
            for (int j = 0; j < 4; ++j)
                hs[sDn][j] = raw[sDn][j] + raw[sDn][j + 1] + raw[sDn][j + 2];
        }

        float o[4];
        if (!edge) {
            // ---- interior fast path: coeff = 1, cnt = 4 ----
#pragma unroll
            for (int j = 0; j < 4; ++j) {
                float v = raw[sMid][j + 1];
                float sum9 = hs[sUp][j] + hs[sMid][j] + hs[sDn][j];
                float mean = sum9 * (1.0f / 9.0f);
                bool mask = (v > THRE_TIMES * mean) || (v > THRE_POINT);
                float nsum = raw[sUp][j + 1] + raw[sDn][j + 1]
                           + raw[sMid][j] + raw[sMid][j + 2];
                float rep = floorf(nsum * 0.25f);
                o[j] = mask ? rep : v;
            }
        } else {
            // ---- boundary path: full logic ----
            const bool rtop = (r == 0);
            const bool rbot = (r == H - 1);
            const float cnt_row = (float)((r > 0) + (r < H - 1));
#pragma unroll
            for (int j = 0; j < 4; ++j) {
                int c = c4 + j;
                float v = raw[sMid][j + 1];
                float sum9 = hs[sUp][j] + hs[sMid][j] + hs[sDn][j];
                float mean = sum9 * (1.0f / 9.0f);
                bool cl = (c == 0), cr = (c == W - 1);
                float coeff = 1.0f;
                if (rtop || rbot || cl || cr)
                    coeff = ((rtop || rbot) && (cl || cr)) ? 2.25f : 1.5f;
                bool mask = (v > THRE_TIMES * mean * coeff) || (v > THRE_POINT);
                float nsum = raw[sUp][j + 1] + raw[sDn][j + 1]
                           + raw[sMid][j] + raw[sMid][j + 2];
                float cnt = cnt_row + (float)((c > 0) + (c < W - 1));
                float rep = floorf(nsum / cnt);
                o[j] = mask ? rep : v;
            }
        }

        float4 res = make_float4(o[0], o[1], o[2], o[3]);
        *reinterpret_cast<float4*>(out + (size_t)r * W + c4) = res;
    }
}

extern "C" void kernel_launch(void* const* d_in, const int* in_sizes, int n_in,
                              void* d_out, int out_size)
{
    const float* img = (const float*)d_in[0];
    float* out = (float*)d_out;

    int n = in_sizes[0];
    int W = (int)(sqrt((double)n) + 0.5);
    int H = n / W;

    dim3 block(64, 4);
    dim3 grid(((W >> 2) + block.x - 1) / block.x,
              (H + (block.y * RPT) - 1) / (block.y * RPT));
    damaged_point_repair_kernel<<<grid, block>>>(img, out, H, W);
}

// round 3
// speedup vs baseline: 1.4795x; 1.1731x over previous
#include <cuda_runtime.h>
#include <math.h>

#define THRE_TIMES 5.0f
#define THRE_POINT 1000.0f
#define RPT 4   // output rows per thread

// ---------------------------------------------------------------------------
// Fast kernel: warp = 128 contiguous columns (32 lanes x float4), halos via
// shuffle, all (RPT+2) row loads front-batched for MLP.
// Requires W % 128 == 0, H % (8*RPT) == 0.
// ---------------------------------------------------------------------------
__global__ __launch_bounds__(256) void dpr_shfl_kernel(
    const float* __restrict__ img, float* __restrict__ out, int H, int W)
{
    const int lane = threadIdx.x;                       // 0..31
    const int c4   = (blockIdx.x * 32 + lane) * 4;      // first of 4 columns
    const int r0   = (blockIdx.y * blockDim.y + threadIdx.y) * RPT;

    float4 arr[RPT + 2];
    float  lft[RPT + 2], rgt[RPT + 2];

    // Front-batched vector loads (rows r0-1 .. r0+RPT)
#pragma unroll
    for (int s = 0; s < RPT + 2; ++s) {
        int rr = r0 - 1 + s;
        if (rr >= 0 && rr < H)
            arr[s] = *reinterpret_cast<const float4*>(img + (size_t)rr * W + c4);
        else
            arr[s] = make_float4(0.f, 0.f, 0.f, 0.f);
    }

    // Halos: neighbor lanes via shuffle; lanes 0/31 patch from global (2 LDG/warp/row)
#pragma unroll
    for (int s = 0; s < RPT + 2; ++s) {
        int rr = r0 - 1 + s;
        bool valid = (rr >= 0) && (rr < H);
        float lw = __shfl_up_sync(0xffffffffu, arr[s].w, 1);
        float rw = __shfl_down_sync(0xffffffffu, arr[s].x, 1);
        if (lane == 0)
            lw = (valid && c4 > 0) ? __ldg(img + (size_t)rr * W + c4 - 1) : 0.0f;
        if (lane == 31)
            rw = (valid && c4 + 4 < W) ? __ldg(img + (size_t)rr * W + c4 + 4) : 0.0f;
        lft[s] = lw; rgt[s] = rw;
    }

    const bool colEdge = (c4 == 0) | (c4 + 4 >= W);
    const bool rowEdge = (r0 == 0) | (r0 + RPT >= H);
    const bool edge = colEdge | rowEdge;

#pragma unroll
    for (int ri = 0; ri < RPT; ++ri) {
        const int r = r0 + ri;
        const float4 up  = arr[ri];
        const float4 mid = arr[ri + 1];
        const float4 dn  = arr[ri + 2];
        const float lm = lft[ri + 1], rm = rgt[ri + 1];

        // horizontal 3-sums for the three rows
        float hsU[4], hsM[4], hsD[4];
        hsU[0] = lft[ri] + up.x + up.y;  hsU[1] = up.x + up.y + up.z;
        hsU[2] = up.y + up.z + up.w;     hsU[3] = up.z + up.w + rgt[ri];
        hsM[0] = lm + mid.x + mid.y;     hsM[1] = mid.x + mid.y + mid.z;
        hsM[2] = mid.y + mid.z + mid.w;  hsM[3] = mid.z + mid.w + rm;
        hsD[0] = lft[ri + 2] + dn.x + dn.y;  hsD[1] = dn.x + dn.y + dn.z;
        hsD[2] = dn.y + dn.z + dn.w;         hsD[3] = dn.z + dn.w + rgt[ri + 2];

        float v[4]  = { mid.x, mid.y, mid.z, mid.w };
        float ns[4];
        ns[0] = up.x + dn.x + lm + mid.y;
        ns[1] = up.y + dn.y + mid.x + mid.z;
        ns[2] = up.z + dn.z + mid.y + mid.w;
        ns[3] = up.w + dn.w + mid.z + rm;

        float o[4];
        if (!edge) {
#pragma unroll
            for (int j = 0; j < 4; ++j) {
                float sum9 = hsU[j] + hsM[j] + hsD[j];
                float mean = sum9 * (1.0f / 9.0f);
                bool mask = (v[j] > THRE_TIMES * mean) || (v[j] > THRE_POINT);
                float rep = floorf(ns[j] * 0.25f);
                o[j] = mask ? rep : v[j];
            }
        } else {
            const bool rtop = (r == 0);
            const bool rbot = (r == H - 1);
            const float cnt_row = (float)((r > 0) + (r < H - 1));
#pragma unroll
            for (int j = 0; j < 4; ++j) {
                int c = c4 + j;
                float sum9 = hsU[j] + hsM[j] + hsD[j];
                float mean = sum9 * (1.0f / 9.0f);
                bool cl = (c == 0), cr = (c == W - 1);
                float coeff = 1.0f;
                if (rtop || rbot || cl || cr)
                    coeff = ((rtop || rbot) && (cl || cr)) ? 2.25f : 1.5f;
                bool mask = (v[j] > THRE_TIMES * mean * coeff) || (v[j] > THRE_POINT);
                float cnt = cnt_row + (float)((c > 0) + (c < W - 1));
                float rep = floorf(ns[j] / cnt);
                o[j] = mask ? rep : v[j];
            }
        }

        *reinterpret_cast<float4*>(out + (size_t)r * W + c4) =
            make_float4(o[0], o[1], o[2], o[3]);
    }
}

// ---------------------------------------------------------------------------
// Generic fallback (R2 kernel) for shapes not matching the warp tile.
// ---------------------------------------------------------------------------
__global__ __launch_bounds__(256) void dpr_generic_kernel(
    const float* __restrict__ img, float* __restrict__ out, int H, int W)
{
    const int Wq = (W + 3) >> 2;
    const int qx = blockIdx.x * blockDim.x + threadIdx.x;
    if (qx >= Wq) return;
    const int c4 = qx << 2;
    const int r = blockIdx.y * blockDim.y + threadIdx.y;
    if (r >= H) return;

    float rowv[3][6];
#pragma unroll
    for (int k = 0; k < 3; ++k) {
        int rr = r + k - 1;
        if (rr < 0 || rr >= H) {
#pragma unroll
            for (int j = 0; j < 6; ++j) rowv[k][j] = 0.0f;
        } else {
            const float* p = img + (size_t)rr * W + c4;
#pragma unroll
            for (int j = 0; j < 4; ++j)
                rowv[k][j + 1] = (c4 + j < W) ? p[j] : 0.0f;
            rowv[k][0] = (c4 > 0) ? p[-1] : 0.0f;
            rowv[k][5] = (c4 + 4 < W) ? p[4] : 0.0f;
        }
    }
    const bool rtop = (r == 0), rbot = (r == H - 1);
    const float cnt_row = (float)((r > 0) + (r < H - 1));
#pragma unroll
    for (int j = 0; j < 4; ++j) {
        int c = c4 + j;
        if (c >= W) break;
        float v = rowv[1][j + 1];
        float sum9 = rowv[0][j] + rowv[0][j + 1] + rowv[0][j + 2]
                   + rowv[1][j] + rowv[1][j + 1] + rowv[1][j + 2]
                   + rowv[2][j] + rowv[2][j + 1] + rowv[2][j + 2];
        float mean = sum9 * (1.0f / 9.0f);
        bool cl = (c == 0), cr = (c == W - 1);
        float coeff = 1.0f;
        if (rtop || rbot || cl || cr)
            coeff = ((rtop || rbot) && (cl || cr)) ? 2.25f : 1.5f;
        bool mask = (v > THRE_TIMES * mean * coeff) || (v > THRE_POINT);
        float nsum = rowv[0][j + 1] + rowv[2][j + 1] + rowv[1][j] + rowv[1][j + 2];
        float cnt = cnt_row + (float)((c > 0) + (c < W - 1));
        out[(size_t)r * W + c] = mask ? floorf(nsum / cnt) : v;
    }
}

extern "C" void kernel_launch(void* const* d_in, const int* in_sizes, int n_in,
                              void* d_out, int out_size)
{
    const float* img = (const float*)d_in[0];
    float* out = (float*)d_out;

    int n = in_sizes[0];
    int W = (int)(sqrt((double)n) + 0.5);
    int H = n / W;

    if (W % 128 == 0 && H % (8 * RPT) == 0) {
        dim3 block(32, 8);
        dim3 grid(W / 128, H / (8 * RPT));
        dpr_shfl_kernel<<<grid, block>>>(img, out, H, W);
    } else {
        dim3 block(64, 4);
        dim3 grid(((W + 3) / 4 + block.x - 1) / block.x,
                  (H + block.y - 1) / block.y);
        dpr_generic_kernel<<<grid, block>>>(img, out, H, W);
    }
}